// round 5
// baseline (speedup 1.0000x reference)
#include <cuda_runtime.h>
#include <cuda_bf16.h>
#include <math.h>
#include <stdint.h>

#define N_NODES 100000
#define N_EDGES 1600000
#define D 128
#define N_LAYERS 4
#define N_GRAPHS 512
#define LN_EPS 1e-5f
#define NB_SCAN 391   // ceil(N_NODES/256)

// ---------------- scratch (device globals; no allocation allowed) ----------------
__device__ __align__(16) __nv_bfloat16 g_hb[N_NODES * D]; // post-GEMM feats, bf16, pre-scaled by dis
__device__ __align__(16) float g_cur[N_NODES * D];        // current layer features (fp32)
__device__ int   g_rowptr[N_NODES + 1];
__device__ int   g_cnt[N_NODES];        // in-degree counts, then CSR cursor
__device__ int   g_esrc[N_EDGES];       // edge sources grouped by dst
__device__ __align__(16) float g_dis[N_NODES];        // deg^{-1/2} (with self loop)
__device__ __align__(16) float g_pool[N_GRAPHS * D];
__device__ __align__(16) float g_pcnt[N_GRAPHS];
__device__ int g_bsum[NB_SCAN + 1];
__device__ int g_boff[NB_SCAN + 1];
__device__ int g_is64_ei;
__device__ int g_is64_b;

// ---------------- helpers ----------------
__device__ __forceinline__ int load_idx(const void* p, long long i, int is64) {
    return is64 ? (int)((const long long*)p)[i] : ((const int*)p)[i];
}

__device__ __forceinline__ uint32_t to_tf32(float f) {
    uint32_t u;
    asm("cvt.rna.tf32.f32 %0, %1;" : "=r"(u) : "f"(f));
    return u;
}

__device__ __forceinline__ void mma_tf32(float* c, const uint32_t* a, const uint32_t* b) {
    asm volatile(
        "mma.sync.aligned.m16n8k8.row.col.f32.tf32.tf32.f32 "
        "{%0,%1,%2,%3}, {%4,%5,%6,%7}, {%8,%9}, {%0,%1,%2,%3};"
        : "+f"(c[0]), "+f"(c[1]), "+f"(c[2]), "+f"(c[3])
        : "r"(a[0]), "r"(a[1]), "r"(a[2]), "r"(a[3]), "r"(b[0]), "r"(b[1]));
}

// ---------------- 0. dtype detector ----------------
// Sample odd int32 slots: int64 (nonneg < 2^31, LE) has zero high-words there.
__global__ void detect_kernel(const int* __restrict__ ei32, int n_e,
                              const int* __restrict__ b32,  int n_b) {
    __shared__ int cnt_e, cnt_b;
    if (threadIdx.x == 0) { cnt_e = 0; cnt_b = 0; }
    __syncthreads();
    for (int k = threadIdx.x; k < 256; k += blockDim.x) {
        long long pe = (long long)(2 * k + 1) * n_e / 512;
        pe |= 1; if (pe >= n_e) pe = (n_e - 1) | 1;
        if (pe < n_e && ei32[pe] != 0) atomicAdd(&cnt_e, 1);
        long long pb = (long long)(2 * k + 1) * n_b / 512;
        pb |= 1; if (pb >= n_b) pb = (n_b - 1) | 1;
        if (pb < n_b && b32[pb] != 0) atomicAdd(&cnt_b, 1);
    }
    __syncthreads();
    if (threadIdx.x == 0) {
        g_is64_ei = (cnt_e == 0) ? 1 : 0;
        g_is64_b  = (cnt_b == 0) ? 1 : 0;
    }
}

// ---------------- 1. zero counters ----------------
__global__ void zero_kernel() {
    int i = blockIdx.x * blockDim.x + threadIdx.x;
    if (i < N_NODES) g_cnt[i] = 0;
    if (i < N_GRAPHS * D) g_pool[i] = 0.f;
    if (i < N_GRAPHS) g_pcnt[i] = 0.f;
}

// ---------------- 2. in-degree histogram ----------------
__global__ void hist_kernel(const void* __restrict__ ei) {
    int i = blockIdx.x * blockDim.x + threadIdx.x;
    if (i >= N_EDGES) return;
    int dst = load_idx(ei, (long long)N_EDGES + i, g_is64_ei);
    atomicAdd(&g_cnt[dst], 1);
}

// ---------------- 3a. per-block reduce of g_cnt ----------------
__global__ __launch_bounds__(256) void scan_reduce_kernel() {
    int t = threadIdx.x, b = blockIdx.x;
    int i = b * 256 + t;
    int v = (i < N_NODES) ? g_cnt[i] : 0;
    int s = v;
#pragma unroll
    for (int off = 16; off > 0; off >>= 1) s += __shfl_xor_sync(0xffffffffu, s, off);
    __shared__ int ws[8];
    if ((t & 31) == 0) ws[t >> 5] = s;
    __syncthreads();
    if (t == 0) {
        int tot = 0;
#pragma unroll
        for (int w = 0; w < 8; ++w) tot += ws[w];
        g_bsum[b] = tot;
    }
}

// ---------------- 3b. scan block sums (single block, 512 thr) ----------------
__global__ __launch_bounds__(512) void scan_bsum_kernel() {
    __shared__ int s[512];
    int t = threadIdx.x;
    int v = (t < NB_SCAN) ? g_bsum[t] : 0;
    s[t] = v;
    __syncthreads();
#pragma unroll
    for (int off = 1; off < 512; off <<= 1) {
        int n = (t >= off) ? s[t - off] : 0;
        __syncthreads();
        s[t] += n;
        __syncthreads();
    }
    if (t < NB_SCAN) g_boff[t] = s[t] - v;   // exclusive
    if (t == 511) g_rowptr[N_NODES] = s[511];
}

// ---------------- 3c. per-block exclusive scan + global offset ----------------
__global__ __launch_bounds__(256) void scan_block_kernel() {
    int t = threadIdx.x, b = blockIdx.x;
    int lane = t & 31, wid = t >> 5;
    int i = b * 256 + t;
    int v = (i < N_NODES) ? g_cnt[i] : 0;
    int incl = v;
#pragma unroll
    for (int off = 1; off < 32; off <<= 1) {
        int n = __shfl_up_sync(0xffffffffu, incl, off);
        if (lane >= off) incl += n;
    }
    __shared__ int wsum[8], woff[8];
    if (lane == 31) wsum[wid] = incl;
    __syncthreads();
    if (wid == 0 && lane < 8) {
        int wv = wsum[lane];
        int wi = wv;
#pragma unroll
        for (int off = 1; off < 8; off <<= 1) {
            int n = __shfl_up_sync(0xffu, wi, off);
            if (lane >= off) wi += n;
        }
        woff[lane] = wi - wv;
    }
    __syncthreads();
    if (i < N_NODES) g_rowptr[i] = g_boff[b] + woff[wid] + (incl - v);
}

// ---------------- 4. deg_inv_sqrt + cursor init ----------------
__global__ void prep_kernel() {
    int v = blockIdx.x * blockDim.x + threadIdx.x;
    if (v >= N_NODES) return;
    g_dis[v] = rsqrtf((float)g_cnt[v] + 1.0f);
    g_cnt[v] = g_rowptr[v];   // becomes CSR fill cursor
}

// ---------------- 5. CSR fill ----------------
__global__ void fill_kernel(const void* __restrict__ ei) {
    int i = blockIdx.x * blockDim.x + threadIdx.x;
    if (i >= N_EDGES) return;
    int is64 = g_is64_ei;
    int src = load_idx(ei, i, is64);
    int dst = load_idx(ei, (long long)N_EDGES + i, is64);
    int pos = atomicAdd(&g_cnt[dst], 1);
    g_esrc[pos] = src;
}

// ---------------- 6. split-TF32 tensor-core GEMM + scaled-bf16 epilogue ----------
// out_bf16[v, :] = bf16( (A @ W)[v, :] * dis[v] )
// 128x128 block tile, 8 warps of 32x64, m16n8k8, 3-MMA TF32 error compensation.
#define GEMM_SMEM_U32 ((128 * 36 + 32 * 132) * 2)
__global__ __launch_bounds__(256) void gemm_tc_kernel(const float* __restrict__ A,
                                                      const float* __restrict__ W,
                                                      __nv_bfloat16* __restrict__ outb) {
    extern __shared__ uint32_t dynsmem[];
    uint32_t* sXhi = dynsmem;                 // 128*36
    uint32_t* sXlo = sXhi + 128 * 36;
    uint32_t* sWhi = sXlo + 128 * 36;         // 32*132
    uint32_t* sWlo = sWhi + 32 * 132;

    int tid = threadIdx.x;
    int lane = tid & 31, wid = tid >> 5;
    int warp_m = wid >> 1, warp_n = wid & 1;
    int tg = lane >> 2, tc = lane & 3;
    int br = blockIdx.x * 128;

    float acc[2][8][4];
#pragma unroll
    for (int mt = 0; mt < 2; ++mt)
#pragma unroll
        for (int nt = 0; nt < 8; ++nt)
#pragma unroll
            for (int q = 0; q < 4; ++q) acc[mt][nt][q] = 0.f;

    for (int kc = 0; kc < 4; ++kc) {
        int k0 = kc * 32;
#pragma unroll
        for (int it = 0; it < 4; ++it) {
            int idx = tid + it * 256;
            int row = idx >> 3, kq = idx & 7;
            float4 v = make_float4(0.f, 0.f, 0.f, 0.f);
            if (br + row < N_NODES)
                v = *(const float4*)&A[(size_t)(br + row) * D + k0 + kq * 4];
            uint32_t hx = to_tf32(v.x), hy = to_tf32(v.y), hz = to_tf32(v.z), hw = to_tf32(v.w);
            *(uint4*)&sXhi[row * 36 + kq * 4] = make_uint4(hx, hy, hz, hw);
            *(uint4*)&sXlo[row * 36 + kq * 4] = make_uint4(
                to_tf32(v.x - __uint_as_float(hx)), to_tf32(v.y - __uint_as_float(hy)),
                to_tf32(v.z - __uint_as_float(hz)), to_tf32(v.w - __uint_as_float(hw)));
        }
#pragma unroll
        for (int it = 0; it < 4; ++it) {
            int idx = tid + it * 256;
            int k = idx >> 5, q = idx & 31;
            float4 v = *(const float4*)&W[(size_t)(k0 + k) * D + q * 4];
            uint32_t hx = to_tf32(v.x), hy = to_tf32(v.y), hz = to_tf32(v.z), hw = to_tf32(v.w);
            *(uint4*)&sWhi[k * 132 + q * 4] = make_uint4(hx, hy, hz, hw);
            *(uint4*)&sWlo[k * 132 + q * 4] = make_uint4(
                to_tf32(v.x - __uint_as_float(hx)), to_tf32(v.y - __uint_as_float(hy)),
                to_tf32(v.z - __uint_as_float(hz)), to_tf32(v.w - __uint_as_float(hw)));
        }
        __syncthreads();

#pragma unroll
        for (int kk = 0; kk < 4; ++kk) {
            uint32_t ah[2][4], al[2][4], bh[8][2], bl[8][2];
#pragma unroll
            for (int mt = 0; mt < 2; ++mt) {
                int r0 = warp_m * 32 + mt * 16 + tg;
                int o0 = r0 * 36 + kk * 8 + tc;
                int o1 = (r0 + 8) * 36 + kk * 8 + tc;
                ah[mt][0] = sXhi[o0]; ah[mt][1] = sXhi[o1];
                ah[mt][2] = sXhi[o0 + 4]; ah[mt][3] = sXhi[o1 + 4];
                al[mt][0] = sXlo[o0]; al[mt][1] = sXlo[o1];
                al[mt][2] = sXlo[o0 + 4]; al[mt][3] = sXlo[o1 + 4];
            }
#pragma unroll
            for (int nt = 0; nt < 8; ++nt) {
                int n0 = warp_n * 64 + nt * 8 + tg;
                int p0 = (kk * 8 + tc) * 132 + n0;
                int p1 = (kk * 8 + 4 + tc) * 132 + n0;
                bh[nt][0] = sWhi[p0]; bh[nt][1] = sWhi[p1];
                bl[nt][0] = sWlo[p0]; bl[nt][1] = sWlo[p1];
            }
#pragma unroll
            for (int mt = 0; mt < 2; ++mt)
#pragma unroll
                for (int nt = 0; nt < 8; ++nt) {
                    mma_tf32(acc[mt][nt], ah[mt], bh[nt]);
                    mma_tf32(acc[mt][nt], ah[mt], bl[nt]);
                    mma_tf32(acc[mt][nt], al[mt], bh[nt]);
                }
        }
        __syncthreads();
    }

#pragma unroll
    for (int mt = 0; mt < 2; ++mt) {
        int r0 = br + warp_m * 32 + mt * 16 + tg;
        float ds0 = (r0 < N_NODES) ? g_dis[r0] : 0.f;
        float ds1 = (r0 + 8 < N_NODES) ? g_dis[r0 + 8] : 0.f;
#pragma unroll
        for (int nt = 0; nt < 8; ++nt) {
            int c0 = warp_n * 64 + nt * 8 + 2 * tc;
            if (r0 < N_NODES) {
                __nv_bfloat162 p = __floats2bfloat162_rn(acc[mt][nt][0] * ds0,
                                                         acc[mt][nt][1] * ds0);
                *(__nv_bfloat162*)&outb[(size_t)r0 * D + c0] = p;
            }
            if (r0 + 8 < N_NODES) {
                __nv_bfloat162 p = __floats2bfloat162_rn(acc[mt][nt][2] * ds1,
                                                         acc[mt][nt][3] * ds1);
                *(__nv_bfloat162*)&outb[(size_t)(r0 + 8) * D + c0] = p;
            }
        }
    }
}

// ---------------- 7. fused aggregation + bias + LN + residual/relu (+pool) -------
// one warp per node; row = 128 bf16 = one uint2 (4 vals) per lane.
// hb is pre-scaled by dis: result = dv*(sum hb[s] + hb[v]) + bias
// mode 0: relu (layer 0); mode 1: +residual, relu; mode 2: +residual, fused pool
__global__ __launch_bounds__(256) void agg_kernel(const float* __restrict__ b,
                                                  const float* __restrict__ gamma,
                                                  const float* __restrict__ beta,
                                                  const void* __restrict__ batch,
                                                  int mode) {
    int warp = (blockIdx.x * blockDim.x + threadIdx.x) >> 5;
    int lane = threadIdx.x & 31;
    if (warp >= N_NODES) return;
    int v = warp;

    const uint2* hb = (const uint2*)g_hb;   // 32 uint2 per row
    float4* cur4 = (float4*)g_cur;

    int beg = g_rowptr[v];
    int end = g_rowptr[v + 1];

    float4 acc = make_float4(0.f, 0.f, 0.f, 0.f);
    int e = beg;
    for (; e + 4 <= end; e += 4) {
        int s0 = __ldg(&g_esrc[e]);
        int s1 = __ldg(&g_esrc[e + 1]);
        int s2 = __ldg(&g_esrc[e + 2]);
        int s3 = __ldg(&g_esrc[e + 3]);
        uint2 u0 = hb[(size_t)s0 * 32 + lane];
        uint2 u1 = hb[(size_t)s1 * 32 + lane];
        uint2 u2 = hb[(size_t)s2 * 32 + lane];
        uint2 u3 = hb[(size_t)s3 * 32 + lane];
#pragma unroll
        for (int q = 0; q < 4; ++q) {
            uint2 u = (q == 0) ? u0 : (q == 1) ? u1 : (q == 2) ? u2 : u3;
            float2 f0 = __bfloat1622float2(*(__nv_bfloat162*)&u.x);
            float2 f1 = __bfloat1622float2(*(__nv_bfloat162*)&u.y);
            acc.x += f0.x; acc.y += f0.y; acc.z += f1.x; acc.w += f1.y;
        }
    }
    for (; e < end; ++e) {
        int s = __ldg(&g_esrc[e]);
        uint2 u = hb[(size_t)s * 32 + lane];
        float2 f0 = __bfloat1622float2(*(__nv_bfloat162*)&u.x);
        float2 f1 = __bfloat1622float2(*(__nv_bfloat162*)&u.y);
        acc.x += f0.x; acc.y += f0.y; acc.z += f1.x; acc.w += f1.y;
    }

    // self loop: hb[v] (already h*dv); then scale all by dv; + bias
    {
        uint2 u = hb[(size_t)v * 32 + lane];
        float2 f0 = __bfloat1622float2(*(__nv_bfloat162*)&u.x);
        float2 f1 = __bfloat1622float2(*(__nv_bfloat162*)&u.y);
        acc.x += f0.x; acc.y += f0.y; acc.z += f1.x; acc.w += f1.y;
    }
    float dv = g_dis[v];
    float4 bb = ((const float4*)b)[lane];
    acc.x = fmaf(acc.x, dv, bb.x);
    acc.y = fmaf(acc.y, dv, bb.y);
    acc.z = fmaf(acc.z, dv, bb.z);
    acc.w = fmaf(acc.w, dv, bb.w);

    // LayerNorm across 128 (warp reduce)
    float s1v = acc.x + acc.y + acc.z + acc.w;
    float s2v = acc.x * acc.x + acc.y * acc.y + acc.z * acc.z + acc.w * acc.w;
#pragma unroll
    for (int off = 16; off > 0; off >>= 1) {
        s1v += __shfl_xor_sync(0xffffffffu, s1v, off);
        s2v += __shfl_xor_sync(0xffffffffu, s2v, off);
    }
    float mu = s1v * (1.0f / 128.0f);
    float var = fmaf(s2v, 1.0f / 128.0f, -mu * mu);
    float inv = rsqrtf(var + LN_EPS);

    float4 g4 = ((const float4*)gamma)[lane];
    float4 be4 = ((const float4*)beta)[lane];
    float4 r;
    r.x = fmaf((acc.x - mu) * inv, g4.x, be4.x);
    r.y = fmaf((acc.y - mu) * inv, g4.y, be4.y);
    r.z = fmaf((acc.z - mu) * inv, g4.z, be4.z);
    r.w = fmaf((acc.w - mu) * inv, g4.w, be4.w);

    if (mode >= 1) {
        float4 res = cur4[(size_t)v * 32 + lane];
        r.x += res.x; r.y += res.y; r.z += res.z; r.w += res.w;
    }
    if (mode != 2) {
        r.x = fmaxf(r.x, 0.f); r.y = fmaxf(r.y, 0.f);
        r.z = fmaxf(r.z, 0.f); r.w = fmaxf(r.w, 0.f);
        cur4[(size_t)v * 32 + lane] = r;
    } else {
        // final layer: pool directly, skip writeback
        int g = load_idx(batch, v, g_is64_b);
        float* dst = &g_pool[(size_t)g * D + lane * 4];
        asm volatile("red.global.add.v4.f32 [%0], {%1, %2, %3, %4};"
                     :: "l"(dst), "f"(r.x), "f"(r.y), "f"(r.z), "f"(r.w)
                     : "memory");
        if (lane == 0) atomicAdd(&g_pcnt[g], 1.0f);
    }
}

// ---------------- 9. final linear ----------------
__global__ void final_kernel(const float* __restrict__ lin_w,
                             const float* __restrict__ lin_b,
                             float* __restrict__ out) {
    int g = blockIdx.x;
    int t = threadIdx.x;   // 128 threads
    float cnt = g_pcnt[g];
    float invc = 1.0f / fmaxf(cnt, 1.0f);
    float val = g_pool[(size_t)g * D + t] * invc * lin_w[t];
#pragma unroll
    for (int off = 16; off > 0; off >>= 1)
        val += __shfl_xor_sync(0xffffffffu, val, off);
    __shared__ float ws[4];
    if ((t & 31) == 0) ws[t >> 5] = val;
    __syncthreads();
    if (t == 0) out[g] = ws[0] + ws[1] + ws[2] + ws[3] + lin_b[0];
}

// ---------------- launch ----------------
extern "C" void kernel_launch(void* const* d_in, const int* in_sizes, int n_in,
                              void* d_out, int out_size) {
    const void* x = 0; const void* ei = 0; const void* batch = 0;
    const void* Ws = 0; const void* lin_w = 0; const void* lin_b = 0;
    const void* small512[3] = {0, 0, 0};
    int n512 = 0;
    for (int i = 0; i < n_in; ++i) {
        switch (in_sizes[i]) {
            case N_NODES * D:      x = d_in[i]; break;
            case 2 * N_EDGES:      ei = d_in[i]; break;
            case N_NODES:          batch = d_in[i]; break;
            case N_LAYERS * D * D: Ws = d_in[i]; break;
            case D:                lin_w = d_in[i]; break;
            case 1:                lin_b = d_in[i]; break;
            case N_LAYERS * D:     if (n512 < 3) small512[n512++] = d_in[i]; break;
            default: break;
        }
    }
    const float* xf      = (const float*)x;
    const float* Wsf     = (const float*)Ws;
    const float* bsf     = (const float*)small512[0];
    const float* gammasf = (const float*)small512[1];
    const float* betasf  = (const float*)small512[2];
    const float* lin_wf  = (const float*)lin_w;
    const float* lin_bf  = (const float*)lin_b;
    float* out = (float*)d_out;

    __nv_bfloat16* hb_ptr; cudaGetSymbolAddress((void**)&hb_ptr, g_hb);
    float* cur_ptr;        cudaGetSymbolAddress((void**)&cur_ptr, g_cur);

    const int gemm_smem = GEMM_SMEM_U32 * 4;   // 70656 B
    cudaFuncSetAttribute(gemm_tc_kernel,
                         cudaFuncAttributeMaxDynamicSharedMemorySize, gemm_smem);

    detect_kernel<<<1, 256>>>((const int*)ei, 2 * N_EDGES, (const int*)batch, N_NODES);

    int zgrid = (N_NODES + 255) / 256;
    if ((N_GRAPHS * D + 255) / 256 > zgrid) zgrid = (N_GRAPHS * D + 255) / 256;
    zero_kernel<<<zgrid, 256>>>();
    hist_kernel<<<(N_EDGES + 255) / 256, 256>>>(ei);
    scan_reduce_kernel<<<NB_SCAN, 256>>>();
    scan_bsum_kernel<<<1, 512>>>();
    scan_block_kernel<<<NB_SCAN, 256>>>();
    prep_kernel<<<(N_NODES + 255) / 256, 256>>>();
    fill_kernel<<<(N_EDGES + 255) / 256, 256>>>(ei);

    int ggrid = (N_NODES + 127) / 128;
    int agrid = (N_NODES * 32 + 255) / 256;
    for (int l = 0; l < N_LAYERS; ++l) {
        const float* A = (l == 0) ? xf : cur_ptr;
        gemm_tc_kernel<<<ggrid, 256, gemm_smem>>>(A, Wsf + (size_t)l * D * D, hb_ptr);
        int mode = (l == 0) ? 0 : (l == N_LAYERS - 1 ? 2 : 1);
        agg_kernel<<<agrid, 256>>>(bsf + (size_t)l * D, gammasf + (size_t)l * D,
                                   betasf + (size_t)l * D, batch, mode);
    }

    final_kernel<<<N_GRAPHS, 128>>>(lin_wf, lin_bf, out);
}

// round 6
// speedup vs baseline: 1.3478x; 1.3478x over previous
#include <cuda_runtime.h>
#include <cuda_bf16.h>
#include <math.h>
#include <stdint.h>

#define N_NODES 100000
#define N_EDGES 1600000
#define D 128
#define N_LAYERS 4
#define N_GRAPHS 512
#define LN_EPS 1e-5f
#define NB_SCAN 391   // ceil(N_NODES/256)

// ---------------- scratch (device globals; no allocation allowed) ----------------
__device__ __align__(16) __nv_bfloat16 g_hb[N_NODES * D]; // post-GEMM feats, bf16, pre-scaled by dis
__device__ __align__(16) float g_cur[N_NODES * D];        // current layer features (fp32)
__device__ int   g_rowptr[N_NODES + 1];
__device__ int   g_cnt[N_NODES];        // in-degree counts, then CSR cursor
__device__ int   g_esrc[N_EDGES];       // edge sources grouped by dst
__device__ __align__(16) float g_dis[N_NODES];        // deg^{-1/2} (with self loop)
__device__ __align__(16) float g_pool[N_GRAPHS * D];
__device__ __align__(16) float g_pcnt[N_GRAPHS];
__device__ int g_bsum[NB_SCAN + 1];
__device__ int g_boff[NB_SCAN + 1];
__device__ int g_is64_ei;
__device__ int g_is64_b;

// ---------------- helpers ----------------
__device__ __forceinline__ int load_idx(const void* p, long long i, int is64) {
    return is64 ? (int)((const long long*)p)[i] : ((const int*)p)[i];
}

__device__ __forceinline__ uint32_t to_tf32(float f) {
    uint32_t u;
    asm("cvt.rna.tf32.f32 %0, %1;" : "=r"(u) : "f"(f));
    return u;
}

__device__ __forceinline__ void mma_tf32(float* c, const uint32_t* a, const uint32_t* b) {
    asm volatile(
        "mma.sync.aligned.m16n8k8.row.col.f32.tf32.tf32.f32 "
        "{%0,%1,%2,%3}, {%4,%5,%6,%7}, {%8,%9}, {%0,%1,%2,%3};"
        : "+f"(c[0]), "+f"(c[1]), "+f"(c[2]), "+f"(c[3])
        : "r"(a[0]), "r"(a[1]), "r"(a[2]), "r"(a[3]), "r"(b[0]), "r"(b[1]));
}

__device__ __forceinline__ void acc8(float* acc, uint4 u) {
    float2 f0 = __bfloat1622float2(*(__nv_bfloat162*)&u.x);
    float2 f1 = __bfloat1622float2(*(__nv_bfloat162*)&u.y);
    float2 f2 = __bfloat1622float2(*(__nv_bfloat162*)&u.z);
    float2 f3 = __bfloat1622float2(*(__nv_bfloat162*)&u.w);
    acc[0] += f0.x; acc[1] += f0.y; acc[2] += f1.x; acc[3] += f1.y;
    acc[4] += f2.x; acc[5] += f2.y; acc[6] += f3.x; acc[7] += f3.y;
}

// ---------------- 0. dtype detector ----------------
// Sample odd int32 slots: int64 (nonneg < 2^31, LE) has zero high-words there.
__global__ void detect_kernel(const int* __restrict__ ei32, int n_e,
                              const int* __restrict__ b32,  int n_b) {
    __shared__ int cnt_e, cnt_b;
    if (threadIdx.x == 0) { cnt_e = 0; cnt_b = 0; }
    __syncthreads();
    for (int k = threadIdx.x; k < 256; k += blockDim.x) {
        long long pe = (long long)(2 * k + 1) * n_e / 512;
        pe |= 1; if (pe >= n_e) pe = (n_e - 1) | 1;
        if (pe < n_e && ei32[pe] != 0) atomicAdd(&cnt_e, 1);
        long long pb = (long long)(2 * k + 1) * n_b / 512;
        pb |= 1; if (pb >= n_b) pb = (n_b - 1) | 1;
        if (pb < n_b && b32[pb] != 0) atomicAdd(&cnt_b, 1);
    }
    __syncthreads();
    if (threadIdx.x == 0) {
        g_is64_ei = (cnt_e == 0) ? 1 : 0;
        g_is64_b  = (cnt_b == 0) ? 1 : 0;
    }
}

// ---------------- 1. zero counters ----------------
__global__ void zero_kernel() {
    int i = blockIdx.x * blockDim.x + threadIdx.x;
    if (i < N_NODES) g_cnt[i] = 0;
    if (i < N_GRAPHS * D) g_pool[i] = 0.f;
    if (i < N_GRAPHS) g_pcnt[i] = 0.f;
}

// ---------------- 2. in-degree histogram ----------------
__global__ void hist_kernel(const void* __restrict__ ei) {
    int i = blockIdx.x * blockDim.x + threadIdx.x;
    if (i >= N_EDGES) return;
    int dst = load_idx(ei, (long long)N_EDGES + i, g_is64_ei);
    atomicAdd(&g_cnt[dst], 1);
}

// ---------------- 3a. per-block reduce of g_cnt ----------------
__global__ __launch_bounds__(256) void scan_reduce_kernel() {
    int t = threadIdx.x, b = blockIdx.x;
    int i = b * 256 + t;
    int v = (i < N_NODES) ? g_cnt[i] : 0;
    int s = v;
#pragma unroll
    for (int off = 16; off > 0; off >>= 1) s += __shfl_xor_sync(0xffffffffu, s, off);
    __shared__ int ws[8];
    if ((t & 31) == 0) ws[t >> 5] = s;
    __syncthreads();
    if (t == 0) {
        int tot = 0;
#pragma unroll
        for (int w = 0; w < 8; ++w) tot += ws[w];
        g_bsum[b] = tot;
    }
}

// ---------------- 3b. scan block sums (single block, 512 thr) ----------------
__global__ __launch_bounds__(512) void scan_bsum_kernel() {
    __shared__ int s[512];
    int t = threadIdx.x;
    int v = (t < NB_SCAN) ? g_bsum[t] : 0;
    s[t] = v;
    __syncthreads();
#pragma unroll
    for (int off = 1; off < 512; off <<= 1) {
        int n = (t >= off) ? s[t - off] : 0;
        __syncthreads();
        s[t] += n;
        __syncthreads();
    }
    if (t < NB_SCAN) g_boff[t] = s[t] - v;   // exclusive
    if (t == 511) g_rowptr[N_NODES] = s[511];
}

// ---------------- 3c. per-block exclusive scan + global offset ----------------
__global__ __launch_bounds__(256) void scan_block_kernel() {
    int t = threadIdx.x, b = blockIdx.x;
    int lane = t & 31, wid = t >> 5;
    int i = b * 256 + t;
    int v = (i < N_NODES) ? g_cnt[i] : 0;
    int incl = v;
#pragma unroll
    for (int off = 1; off < 32; off <<= 1) {
        int n = __shfl_up_sync(0xffffffffu, incl, off);
        if (lane >= off) incl += n;
    }
    __shared__ int wsum[8], woff[8];
    if (lane == 31) wsum[wid] = incl;
    __syncthreads();
    if (wid == 0 && lane < 8) {
        int wv = wsum[lane];
        int wi = wv;
#pragma unroll
        for (int off = 1; off < 8; off <<= 1) {
            int n = __shfl_up_sync(0xffu, wi, off);
            if (lane >= off) wi += n;
        }
        woff[lane] = wi - wv;
    }
    __syncthreads();
    if (i < N_NODES) g_rowptr[i] = g_boff[b] + woff[wid] + (incl - v);
}

// ---------------- 4. deg_inv_sqrt + cursor init ----------------
__global__ void prep_kernel() {
    int v = blockIdx.x * blockDim.x + threadIdx.x;
    if (v >= N_NODES) return;
    g_dis[v] = rsqrtf((float)g_cnt[v] + 1.0f);
    g_cnt[v] = g_rowptr[v];   // becomes CSR fill cursor
}

// ---------------- 5. CSR fill ----------------
__global__ void fill_kernel(const void* __restrict__ ei) {
    int i = blockIdx.x * blockDim.x + threadIdx.x;
    if (i >= N_EDGES) return;
    int is64 = g_is64_ei;
    int src = load_idx(ei, i, is64);
    int dst = load_idx(ei, (long long)N_EDGES + i, is64);
    int pos = atomicAdd(&g_cnt[dst], 1);
    g_esrc[pos] = src;
}

// ---------------- 6. TF32 tensor-core GEMM + scaled-bf16 epilogue ----------------
// outb[v, :] = bf16( (A @ W)[v, :] * dis[v] )
// 128x128 block tile, 8 warps of 32x64, m16n8k8, single-MMA TF32 (R4 version).
__global__ __launch_bounds__(256) void gemm_tc_kernel(const float* __restrict__ A,
                                                      const float* __restrict__ W,
                                                      __nv_bfloat16* __restrict__ outb) {
    __shared__ uint32_t sX[128 * 36];   // stride 36 -> conflict-free A frags
    __shared__ uint32_t sW[32 * 132];   // stride 132 -> <=2-way on B frags
    int tid = threadIdx.x;
    int lane = tid & 31, wid = tid >> 5;
    int warp_m = wid >> 1, warp_n = wid & 1;
    int tg = lane >> 2, tc = lane & 3;
    int br = blockIdx.x * 128;

    float acc[2][8][4];
#pragma unroll
    for (int mt = 0; mt < 2; ++mt)
#pragma unroll
        for (int nt = 0; nt < 8; ++nt)
#pragma unroll
            for (int q = 0; q < 4; ++q) acc[mt][nt][q] = 0.f;

    for (int kc = 0; kc < 4; ++kc) {
        int k0 = kc * 32;
#pragma unroll
        for (int it = 0; it < 4; ++it) {
            int idx = tid + it * 256;
            int row = idx >> 3, kq = idx & 7;
            float4 v = make_float4(0.f, 0.f, 0.f, 0.f);
            if (br + row < N_NODES)
                v = *(const float4*)&A[(size_t)(br + row) * D + k0 + kq * 4];
            uint4 u = make_uint4(to_tf32(v.x), to_tf32(v.y), to_tf32(v.z), to_tf32(v.w));
            *(uint4*)&sX[row * 36 + kq * 4] = u;
        }
#pragma unroll
        for (int it = 0; it < 4; ++it) {
            int idx = tid + it * 256;
            int k = idx >> 5, q = idx & 31;
            float4 v = *(const float4*)&W[(size_t)(k0 + k) * D + q * 4];
            uint4 u = make_uint4(to_tf32(v.x), to_tf32(v.y), to_tf32(v.z), to_tf32(v.w));
            *(uint4*)&sW[k * 132 + q * 4] = u;
        }
        __syncthreads();

#pragma unroll
        for (int kk = 0; kk < 4; ++kk) {
            uint32_t a[2][4], b[8][2];
#pragma unroll
            for (int mt = 0; mt < 2; ++mt) {
                int r0 = warp_m * 32 + mt * 16 + tg;
                a[mt][0] = sX[r0 * 36 + kk * 8 + tc];
                a[mt][1] = sX[(r0 + 8) * 36 + kk * 8 + tc];
                a[mt][2] = sX[r0 * 36 + kk * 8 + tc + 4];
                a[mt][3] = sX[(r0 + 8) * 36 + kk * 8 + tc + 4];
            }
#pragma unroll
            for (int nt = 0; nt < 8; ++nt) {
                int n0 = warp_n * 64 + nt * 8 + tg;
                b[nt][0] = sW[(kk * 8 + tc) * 132 + n0];
                b[nt][1] = sW[(kk * 8 + 4 + tc) * 132 + n0];
            }
#pragma unroll
            for (int mt = 0; mt < 2; ++mt)
#pragma unroll
                for (int nt = 0; nt < 8; ++nt)
                    mma_tf32(acc[mt][nt], a[mt], b[nt]);
        }
        __syncthreads();
    }

#pragma unroll
    for (int mt = 0; mt < 2; ++mt) {
        int r0 = br + warp_m * 32 + mt * 16 + tg;
        float ds0 = (r0 < N_NODES) ? g_dis[r0] : 0.f;
        float ds1 = (r0 + 8 < N_NODES) ? g_dis[r0 + 8] : 0.f;
#pragma unroll
        for (int nt = 0; nt < 8; ++nt) {
            int c0 = warp_n * 64 + nt * 8 + 2 * tc;
            if (r0 < N_NODES) {
                __nv_bfloat162 p = __floats2bfloat162_rn(acc[mt][nt][0] * ds0,
                                                         acc[mt][nt][1] * ds0);
                *(__nv_bfloat162*)&outb[(size_t)r0 * D + c0] = p;
            }
            if (r0 + 8 < N_NODES) {
                __nv_bfloat162 p = __floats2bfloat162_rn(acc[mt][nt][2] * ds1,
                                                         acc[mt][nt][3] * ds1);
                *(__nv_bfloat162*)&outb[(size_t)(r0 + 8) * D + c0] = p;
            }
        }
    }
}

// ---------------- 7. fused aggregation + bias + LN + residual/relu (+pool) -------
// ONE WARP PER NODE, HALF-WARP EDGE PARALLELISM:
// bf16 row = 256B = 16 lanes x uint4. Lanes 0-15 take even edges, 16-31 odd
// edges of the SAME node; one LDG.128 serves two edge gathers. Halves combined
// by shfl_down(16) before LN. hb is pre-scaled by dis:
//   result = dv*(sum_s hb[s] + hb[v]) + bias
// mode 0: relu (layer 0); mode 1: +residual, relu; mode 2: +residual, fused pool
__global__ __launch_bounds__(256) void agg_kernel(const float* __restrict__ b,
                                                  const float* __restrict__ gamma,
                                                  const float* __restrict__ beta,
                                                  const void* __restrict__ batch,
                                                  int mode) {
    int warp = (blockIdx.x * blockDim.x + threadIdx.x) >> 5;
    int lane = threadIdx.x & 31;
    if (warp >= N_NODES) return;
    int v = warp;
    int h  = lane >> 4;     // half-warp id (edge parity)
    int li = lane & 15;     // lane within half: owns row bytes [16*li, 16*li+16)

    const uint4* hb4 = (const uint4*)g_hb;   // 16 uint4 per row

    int beg = g_rowptr[v];
    int end = g_rowptr[v + 1];

    float acc[8];
#pragma unroll
    for (int q = 0; q < 8; ++q) acc[q] = 0.f;

    int e = beg;
    for (; e + 4 <= end; e += 4) {
        int sA = __ldg(&g_esrc[e + h]);
        int sB = __ldg(&g_esrc[e + 2 + h]);
        uint4 uA = hb4[(size_t)sA * 16 + li];
        uint4 uB = hb4[(size_t)sB * 16 + li];
        acc8(acc, uA);
        acc8(acc, uB);
    }
    if (e + 2 <= end) {
        int s = __ldg(&g_esrc[e + h]);
        uint4 u = hb4[(size_t)s * 16 + li];
        acc8(acc, u);
        e += 2;
    }
    if (e < end && h == 0) {
        int s = __ldg(&g_esrc[e]);
        uint4 u = hb4[(size_t)s * 16 + li];
        acc8(acc, u);
    }

    // combine odd-edge half into lanes 0-15
#pragma unroll
    for (int q = 0; q < 8; ++q)
        acc[q] += __shfl_down_sync(0xffffffffu, acc[q], 16);

    if (h == 0) {
        // self loop (hb[v] already = h*dv), then scale by dv, + bias
        uint4 us = hb4[(size_t)v * 16 + li];
        acc8(acc, us);
        float dv = g_dis[v];
        float4 b0 = ((const float4*)b)[li * 2];
        float4 b1 = ((const float4*)b)[li * 2 + 1];
        acc[0] = fmaf(acc[0], dv, b0.x); acc[1] = fmaf(acc[1], dv, b0.y);
        acc[2] = fmaf(acc[2], dv, b0.z); acc[3] = fmaf(acc[3], dv, b0.w);
        acc[4] = fmaf(acc[4], dv, b1.x); acc[5] = fmaf(acc[5], dv, b1.y);
        acc[6] = fmaf(acc[6], dv, b1.z); acc[7] = fmaf(acc[7], dv, b1.w);

        // LayerNorm across 128 = reduce over 16 lanes x 8 vals
        float s1v = 0.f, s2v = 0.f;
#pragma unroll
        for (int q = 0; q < 8; ++q) { s1v += acc[q]; s2v += acc[q] * acc[q]; }
#pragma unroll
        for (int off = 8; off > 0; off >>= 1) {
            s1v += __shfl_xor_sync(0x0000ffffu, s1v, off);
            s2v += __shfl_xor_sync(0x0000ffffu, s2v, off);
        }
        float mu = s1v * (1.0f / 128.0f);
        float var = fmaf(s2v, 1.0f / 128.0f, -mu * mu);
        float inv = rsqrtf(var + LN_EPS);

        float4 g0 = ((const float4*)gamma)[li * 2];
        float4 g1 = ((const float4*)gamma)[li * 2 + 1];
        float4 e0 = ((const float4*)beta)[li * 2];
        float4 e1 = ((const float4*)beta)[li * 2 + 1];
        float r[8];
        r[0] = fmaf((acc[0] - mu) * inv, g0.x, e0.x);
        r[1] = fmaf((acc[1] - mu) * inv, g0.y, e0.y);
        r[2] = fmaf((acc[2] - mu) * inv, g0.z, e0.z);
        r[3] = fmaf((acc[3] - mu) * inv, g0.w, e0.w);
        r[4] = fmaf((acc[4] - mu) * inv, g1.x, e1.x);
        r[5] = fmaf((acc[5] - mu) * inv, g1.y, e1.y);
        r[6] = fmaf((acc[6] - mu) * inv, g1.z, e1.z);
        r[7] = fmaf((acc[7] - mu) * inv, g1.w, e1.w);

        float4* cur4 = (float4*)g_cur;
        if (mode >= 1) {
            float4 c0 = cur4[(size_t)v * 32 + li * 2];
            float4 c1 = cur4[(size_t)v * 32 + li * 2 + 1];
            r[0] += c0.x; r[1] += c0.y; r[2] += c0.z; r[3] += c0.w;
            r[4] += c1.x; r[5] += c1.y; r[6] += c1.z; r[7] += c1.w;
        }
        if (mode != 2) {
#pragma unroll
            for (int q = 0; q < 8; ++q) r[q] = fmaxf(r[q], 0.f);
            cur4[(size_t)v * 32 + li * 2] = make_float4(r[0], r[1], r[2], r[3]);
            cur4[(size_t)v * 32 + li * 2 + 1] = make_float4(r[4], r[5], r[6], r[7]);
        } else {
            // final layer: pool directly, skip writeback
            int g = load_idx(batch, v, g_is64_b);
            float* dst = &g_pool[(size_t)g * D + li * 8];
            asm volatile("red.global.add.v4.f32 [%0], {%1, %2, %3, %4};"
                         :: "l"(dst), "f"(r[0]), "f"(r[1]), "f"(r[2]), "f"(r[3])
                         : "memory");
            asm volatile("red.global.add.v4.f32 [%0], {%1, %2, %3, %4};"
                         :: "l"(dst + 4), "f"(r[4]), "f"(r[5]), "f"(r[6]), "f"(r[7])
                         : "memory");
            if (lane == 0) atomicAdd(&g_pcnt[g], 1.0f);
        }
    }
}

// ---------------- 9. final linear ----------------
__global__ void final_kernel(const float* __restrict__ lin_w,
                             const float* __restrict__ lin_b,
                             float* __restrict__ out) {
    int g = blockIdx.x;
    int t = threadIdx.x;   // 128 threads
    float cnt = g_pcnt[g];
    float invc = 1.0f / fmaxf(cnt, 1.0f);
    float val = g_pool[(size_t)g * D + t] * invc * lin_w[t];
#pragma unroll
    for (int off = 16; off > 0; off >>= 1)
        val += __shfl_xor_sync(0xffffffffu, val, off);
    __shared__ float ws[4];
    if ((t & 31) == 0) ws[t >> 5] = val;
    __syncthreads();
    if (t == 0) out[g] = ws[0] + ws[1] + ws[2] + ws[3] + lin_b[0];
}

// ---------------- launch ----------------
extern "C" void kernel_launch(void* const* d_in, const int* in_sizes, int n_in,
                              void* d_out, int out_size) {
    const void* x = 0; const void* ei = 0; const void* batch = 0;
    const void* Ws = 0; const void* lin_w = 0; const void* lin_b = 0;
    const void* small512[3] = {0, 0, 0};
    int n512 = 0;
    for (int i = 0; i < n_in; ++i) {
        switch (in_sizes[i]) {
            case N_NODES * D:      x = d_in[i]; break;
            case 2 * N_EDGES:      ei = d_in[i]; break;
            case N_NODES:          batch = d_in[i]; break;
            case N_LAYERS * D * D: Ws = d_in[i]; break;
            case D:                lin_w = d_in[i]; break;
            case 1:                lin_b = d_in[i]; break;
            case N_LAYERS * D:     if (n512 < 3) small512[n512++] = d_in[i]; break;
            default: break;
        }
    }
    const float* xf      = (const float*)x;
    const float* Wsf     = (const float*)Ws;
    const float* bsf     = (const float*)small512[0];
    const float* gammasf = (const float*)small512[1];
    const float* betasf  = (const float*)small512[2];
    const float* lin_wf  = (const float*)lin_w;
    const float* lin_bf  = (const float*)lin_b;
    float* out = (float*)d_out;

    __nv_bfloat16* hb_ptr; cudaGetSymbolAddress((void**)&hb_ptr, g_hb);
    float* cur_ptr;        cudaGetSymbolAddress((void**)&cur_ptr, g_cur);

    detect_kernel<<<1, 256>>>((const int*)ei, 2 * N_EDGES, (const int*)batch, N_NODES);

    int zgrid = (N_NODES + 255) / 256;
    if ((N_GRAPHS * D + 255) / 256 > zgrid) zgrid = (N_GRAPHS * D + 255) / 256;
    zero_kernel<<<zgrid, 256>>>();
    hist_kernel<<<(N_EDGES + 255) / 256, 256>>>(ei);
    scan_reduce_kernel<<<NB_SCAN, 256>>>();
    scan_bsum_kernel<<<1, 512>>>();
    scan_block_kernel<<<NB_SCAN, 256>>>();
    prep_kernel<<<(N_NODES + 255) / 256, 256>>>();
    fill_kernel<<<(N_EDGES + 255) / 256, 256>>>(ei);

    int ggrid = (N_NODES + 127) / 128;
    int agrid = (N_NODES * 32 + 255) / 256;
    for (int l = 0; l < N_LAYERS; ++l) {
        const float* A = (l == 0) ? xf : cur_ptr;
        gemm_tc_kernel<<<ggrid, 256>>>(A, Wsf + (size_t)l * D * D, hb_ptr);
        int mode = (l == 0) ? 0 : (l == N_LAYERS - 1 ? 2 : 1);
        agg_kernel<<<agrid, 256>>>(bsf + (size_t)l * D, gammasf + (size_t)l * D,
                                   betasf + (size_t)l * D, batch, mode);
    }

    final_kernel<<<N_GRAPHS, 128>>>(lin_wf, lin_bf, out);
}